// round 15
// baseline (speedup 1.0000x reference)
#include <cuda_runtime.h>
#include <cuda_bf16.h>
#include <math.h>

#define TT    8192
#define HD    1024
#define G4H   4096
#define NBLK  128               // 128 blocks * 4 warps/dir * 2 units/warp = 1024 units/dir
#define KREG  512               // k < 512 register-resident (4 float4 chunks/lane)
#define KSM   512               // k in [512,1024) in smem
// dynamic smem: weights[8 warps][8 rows][512] + hstage[2][1024]
#define OFF_HS    (8*8*KSM)             // float offset of h stage
#define SMEM_LSTM ((OFF_HS + 2*HD) * 4) // 139264 B

// ---------------- static device scratch ----------------
__device__ float    g_xg[2][TT][G4H];
__device__ float    g_h0[(size_t)TT*2048];
__device__ float    g_h1[(size_t)TT*2048];
__device__ float    g_feats[TT*5];
__device__ float    g_hbuf[2][2][HD];        // [dir][ping][H]
__device__ unsigned g_flagw[2][NBLK];        // per-block step flags (4 lines/dir)

union F2 { float2 f; unsigned long long u; };

__device__ __forceinline__ unsigned ld_acq(const unsigned* p) {
    unsigned v;
    asm volatile("ld.acquire.gpu.global.u32 %0, [%1];" : "=r"(v) : "l"(p) : "memory");
    return v;
}
__device__ __forceinline__ void st_rel(unsigned* p, unsigned v) {
    asm volatile("st.release.gpu.global.u32 [%0], %1;" :: "l"(p), "r"(v) : "memory");
}
__device__ __forceinline__ void bar_named(int id) {
    asm volatile("bar.sync %0, 128;" :: "r"(id) : "memory");
}
__device__ __forceinline__ void fma2(F2& acc, float ax, float ay, float bx, float by) {
    F2 a, b; a.f.x = ax; a.f.y = ay; b.f.x = bx; b.f.y = by;
    asm("fma.rn.f32x2 %0, %1, %2, %0;" : "+l"(acc.u) : "l"(a.u), "l"(b.u));
}

__global__ void init_kernel() {
    int i = blockIdx.x * blockDim.x + threadIdx.x;
    if (i < 2*2*HD) ((float*)g_hbuf)[i] = 0.f;
    if (i < 2*NBLK) ((unsigned*)g_flagw)[i] = 0u;
}

// ---------------- fp32 SGEMM, double-buffered, f32x2 FMA, float4 LDS ----------------
#define BM 128
#define BN 128
#define BK 16
__global__ void __launch_bounds__(256) sgemm_bias(
    const float* __restrict__ A, const float* __restrict__ W,
    const float* __restrict__ b1, const float* __restrict__ b2,
    float* __restrict__ C, int M, int N, int K)
{
    __shared__ float As[2][BK][BM+4];
    __shared__ float Bs[2][BK][BN+4];
    const int tid = threadIdx.x;
    const int bm0 = blockIdx.y * BM;
    const int bn0 = blockIdx.x * BN;
    const int tx = tid & 15, ty = tid >> 4;
    const int lrow = tid >> 2;
    const int lc4  = (tid & 3) * 4;

    F2 acc[8][4];
    #pragma unroll
    for (int i = 0; i < 8; i++)
        #pragma unroll
        for (int j = 0; j < 4; j++) acc[i][j].u = 0ull;

    float4 ra[2], rb[2];
    #pragma unroll
    for (int h = 0; h < 2; h++) {
        int row = lrow + h*64;
        ra[h] = *(const float4*)(A + (size_t)(bm0+row)*K + lc4);
        rb[h] = *(const float4*)(W + (size_t)(bn0+row)*K + lc4);
    }
    #pragma unroll
    for (int h = 0; h < 2; h++) {
        int row = lrow + h*64;
        As[0][lc4+0][row] = ra[h].x; As[0][lc4+1][row] = ra[h].y;
        As[0][lc4+2][row] = ra[h].z; As[0][lc4+3][row] = ra[h].w;
        Bs[0][lc4+0][row] = rb[h].x; Bs[0][lc4+1][row] = rb[h].y;
        Bs[0][lc4+2][row] = rb[h].z; Bs[0][lc4+3][row] = rb[h].w;
    }
    __syncthreads();

    int buf = 0;
    for (int k0 = BK; k0 <= K; k0 += BK) {
        if (k0 < K) {
            #pragma unroll
            for (int h = 0; h < 2; h++) {
                int row = lrow + h*64;
                ra[h] = *(const float4*)(A + (size_t)(bm0+row)*K + k0 + lc4);
                rb[h] = *(const float4*)(W + (size_t)(bn0+row)*K + k0 + lc4);
            }
        }
        #pragma unroll
        for (int kk = 0; kk < BK; kk++) {
            float4 a0 = ((const float4*)&As[buf][kk][ty*8])[0];
            float4 a1 = ((const float4*)&As[buf][kk][ty*8])[1];
            float4 b0 = ((const float4*)&Bs[buf][kk][tx*8])[0];
            float4 b1 = ((const float4*)&Bs[buf][kk][tx*8])[1];
            float a[8] = {a0.x, a0.y, a0.z, a0.w, a1.x, a1.y, a1.z, a1.w};
            F2 bp[4];
            bp[0].f.x = b0.x; bp[0].f.y = b0.y;
            bp[1].f.x = b0.z; bp[1].f.y = b0.w;
            bp[2].f.x = b1.x; bp[2].f.y = b1.y;
            bp[3].f.x = b1.z; bp[3].f.y = b1.w;
            #pragma unroll
            for (int i = 0; i < 8; i++) {
                F2 ap; ap.f.x = a[i]; ap.f.y = a[i];
                #pragma unroll
                for (int j = 0; j < 4; j++)
                    asm("fma.rn.f32x2 %0, %1, %2, %0;" : "+l"(acc[i][j].u) : "l"(ap.u), "l"(bp[j].u));
            }
        }
        if (k0 < K) {
            __syncthreads();
            int nb = buf ^ 1;
            #pragma unroll
            for (int h = 0; h < 2; h++) {
                int row = lrow + h*64;
                As[nb][lc4+0][row] = ra[h].x; As[nb][lc4+1][row] = ra[h].y;
                As[nb][lc4+2][row] = ra[h].z; As[nb][lc4+3][row] = ra[h].w;
                Bs[nb][lc4+0][row] = rb[h].x; Bs[nb][lc4+1][row] = rb[h].y;
                Bs[nb][lc4+2][row] = rb[h].z; Bs[nb][lc4+3][row] = rb[h].w;
            }
            __syncthreads();
            buf = nb;
        }
    }
    float bv[8];
    #pragma unroll
    for (int j = 0; j < 8; j++) { int n = bn0 + tx*8 + j; bv[j] = b1[n] + b2[n]; }
    #pragma unroll
    for (int i = 0; i < 8; i++) {
        size_t mrow = (size_t)(bm0 + ty*8 + i) * N;
        #pragma unroll
        for (int j = 0; j < 4; j++) {
            C[mrow + bn0 + tx*8 + 2*j + 0] = acc[i][j].f.x + bv[2*j+0];
            C[mrow + bn0 + tx*8 + 2*j + 1] = acc[i][j].f.y + bv[2*j+1];
        }
    }
}

// ---------------- persistent bidirectional LSTM (flag slots, acquire polling) ----------------
// 128 blocks x 8 warps; warps 0-3 fwd, 4-7 bwd; warp owns 2 units (8 whole gate
// rows). Per step: ALL 4 warps of the dir group poll lane-per-flag with
// ld.acquire (warp gq, lane l -> flag gq*32+l); bar -> parallel h staging
// (2 float4/thread); bar -> dots -> butterfly -> lane-parallel acts ->
// lanes 0/1 stcg h -> bar -> one st.release flag per block per dir.
__global__ void __launch_bounds__(256, 1) lstm_kernel(
    const float* __restrict__ xgf, const float* __restrict__ xgb,
    const float* __restrict__ whf, const float* __restrict__ whb,
    float* __restrict__ hout)
{
    extern __shared__ float ws[];
    const int tid  = threadIdx.x;
    const int warp = tid >> 5;
    const int lane = tid & 31;
    const int dir  = warp >> 2;
    const int gq   = warp & 3;
    const int gtid = tid & 127;
    const int u0   = blockIdx.x * 8 + gq * 2;

    const float* wh = dir ? whb : whf;
    const float* xg = dir ? xgb : xgf;

    // ---- stage smem weight half (k in [512,1024)) ----
    for (int idx = tid; idx < 8*8*(KSM/4); idx += 256) {
        int w2 = idx >> 10;                 // warp slot 0..7
        int rr = (idx >> 7) & 7;            // row within warp
        int q  = idx & 127;                 // float4 within KSM
        int unit = blockIdx.x * 8 + (w2 & 3) * 2 + (rr & 1);
        int gate = rr >> 1;
        const float* src = ((w2 >> 2) ? whb : whf) + ((size_t)((gate << 10) + unit)) * HD;
        ((float4*)ws)[idx] = __ldg((const float4*)src + (KREG/4) + q);
    }
    // ---- register weight half (k < 512): wreg[8 rows][4 chunks] ----
    float4 wreg[8][4];
    #pragma unroll
    for (int r = 0; r < 8; r++) {
        int unit = u0 + (r & 1);
        int gate = r >> 1;
        const float4* src = (const float4*)(wh + ((size_t)((gate << 10) + unit)) * HD);
        #pragma unroll
        for (int i = 0; i < 4; i++) wreg[r][i] = __ldg(src + (i << 5) + lane);
    }
    __syncthreads();

    const float4* ws_warp = (const float4*)ws + warp * 8 * (KSM/4);
    float4* hs4 = (float4*)(ws + OFF_HS + dir * HD);
    const bool cl = (lane < 2);
    const int  myu = u0 + lane;             // lanes 0,1
    const unsigned* pollp = &g_flagw[dir][(gq << 5) + lane];  // this thread's flag
    unsigned* myflag = &g_flagw[dir][blockIdx.x];
    const int bid = 1 + dir;
    const int du = lane & 1;
    float creg = 0.f;

    #pragma unroll 1
    for (int t = 0; t < TT; t++) {
        const int tt = dir ? (TT-1-t) : t;
        // xg prefetch for lanes 0,1 (DRAM, issued before the wait)
        float xgv0=0.f, xgv1=0.f, xgv2=0.f, xgv3=0.f;
        if (cl) {
            const float* p = xg + (size_t)tt * G4H + myu;
            xgv0 = __ldg(p); xgv1 = __ldg(p+HD); xgv2 = __ldg(p+2*HD); xgv3 = __ldg(p+3*HD);
        }
        // all 4 group warps poll: lane-per-flag acquire spin (32 flags per warp)
        {
            const unsigned tgt = (unsigned)t;
            unsigned ok;
            do {
                ok = (ld_acq(pollp) >= tgt) ? 1u : 0u;
            } while (!__all_sync(0xFFFFFFFFu, ok));
        }
        bar_named(bid);                      // all 128 flags of this dir confirmed
        // parallel h staging: 2 float4 per thread (256 total over 128 threads)
        {
            const float4* hb4 = (const float4*)&g_hbuf[dir][t & 1][0];
            hs4[gtid]       = __ldcg(hb4 + gtid);
            hs4[gtid + 128] = __ldcg(hb4 + gtid + 128);
        }
        bar_named(bid);
        // h into registers from smem
        float4 hv[8];
        #pragma unroll
        for (int i = 0; i < 8; i++) hv[i] = hs4[(i << 5) + lane];
        // 8 complete gate-row dots: 4 chunks regs + 4 chunks smem, f32x2
        F2 acc[8];
        #pragma unroll
        for (int r = 0; r < 8; r++) acc[r].u = 0ull;
        #pragma unroll
        for (int r = 0; r < 8; r++) {
            #pragma unroll
            for (int i = 0; i < 4; i++) {
                float4 w = wreg[r][i];
                fma2(acc[r], w.x, w.y, hv[i].x, hv[i].y);
                fma2(acc[r], w.z, w.w, hv[i].z, hv[i].w);
            }
            const float4* w4s = ws_warp + r * (KSM/4);
            #pragma unroll
            for (int i = 0; i < 4; i++) {
                float4 v = w4s[(i << 5) + lane];
                fma2(acc[r], v.x, v.y, hv[4+i].x, hv[4+i].y);
                fma2(acc[r], v.z, v.w, hv[4+i].z, hv[4+i].w);
            }
        }
        // butterfly reduce: every lane gets all 8 row sums
        float v[8];
        #pragma unroll
        for (int r = 0; r < 8; r++) {
            float s = acc[r].f.x + acc[r].f.y;
            #pragma unroll
            for (int off = 16; off; off >>= 1) s += __shfl_xor_sync(0xFFFFFFFFu, s, off);
            v[r] = s;
        }
        // 8-lane parallel activations: lane l = row l (gate l>>1, unit du=l&1)
        float xg0s = __shfl_sync(0xFFFFFFFFu, xgv0, du);
        float xg1s = __shfl_sync(0xFFFFFFFFu, xgv1, du);
        float xg2s = __shfl_sync(0xFFFFFFFFu, xgv2, du);
        float xg3s = __shfl_sync(0xFFFFFFFFu, xgv3, du);
        int gsel = lane >> 1;
        float xgs = (gsel == 0) ? xg0s : (gsel == 1) ? xg1s : (gsel == 2) ? xg2s : xg3s;
        float vsel = v[0];
        vsel = (lane == 1) ? v[1] : vsel;
        vsel = (lane == 2) ? v[2] : vsel;
        vsel = (lane == 3) ? v[3] : vsel;
        vsel = (lane == 4) ? v[4] : vsel;
        vsel = (lane == 5) ? v[5] : vsel;
        vsel = (lane == 6) ? v[6] : vsel;
        vsel = (lane == 7) ? v[7] : vsel;
        float raw = xgs + vsel;
        float act = (gsel == 2) ? tanhf(raw) : 1.f / (1.f + expf(-raw));
        // gather per-unit gates and update (lanes 0,1)
        float ai = __shfl_sync(0xFFFFFFFFu, act, du);
        float af = __shfl_sync(0xFFFFFFFFu, act, 2 + du);
        float ag = __shfl_sync(0xFFFFFFFFu, act, 4 + du);
        float ao = __shfl_sync(0xFFFFFFFFu, act, 6 + du);
        float h = 0.f;
        if (cl) {
            creg = af * creg + ai * ag;
            h = ao * tanhf(creg);
            __stcg(&g_hbuf[dir][(t+1) & 1][myu], h);
        }
        bar_named(bid);                      // CTA hb: h stores before the release
        if (gtid == 0) st_rel(myflag, (unsigned)(t + 1));   // plain release store
        // hout DRAM store off the signaling critical path
        if (cl) hout[(size_t)tt * 2048 + (dir << 10) + myu] = h;
    }
}

// ---------------- feats = h1 @ w_out^T + b_out (shuffle reduction) ----------------
__global__ void feats_kernel(const float* __restrict__ h1, const float* __restrict__ wout,
                             const float* __restrict__ bout, float* __restrict__ feats)
{
    __shared__ float red[5][8];
    int t = blockIdx.x, tid = threadIdx.x;
    int warp = tid >> 5, lane = tid & 31;
    const float* hrow = h1 + (size_t)t * 2048;
    float p[5] = {0,0,0,0,0};
    for (int k = tid; k < 2048; k += 256) {
        float hv = hrow[k];
        p[0] = fmaf(hv, __ldg(wout + 0*2048 + k), p[0]);
        p[1] = fmaf(hv, __ldg(wout + 1*2048 + k), p[1]);
        p[2] = fmaf(hv, __ldg(wout + 2*2048 + k), p[2]);
        p[3] = fmaf(hv, __ldg(wout + 3*2048 + k), p[3]);
        p[4] = fmaf(hv, __ldg(wout + 4*2048 + k), p[4]);
    }
    #pragma unroll
    for (int g = 0; g < 5; g++) {
        float s = p[g];
        #pragma unroll
        for (int off = 16; off; off >>= 1) s += __shfl_xor_sync(0xFFFFFFFFu, s, off);
        if (lane == 0) red[g][warp] = s;
    }
    __syncthreads();
    if (tid < 5) {
        float s = 0.f;
        #pragma unroll
        for (int i = 0; i < 8; i++) s += red[tid][i];
        feats[t*5 + tid] = s + bout[tid];
    }
}

// ---------------- Viterbi DP + backtrace ----------------
#define NEGV (-10000.0f)
__global__ void viterbi_kernel(const float* __restrict__ feats, const float* __restrict__ trans,
                               float* __restrict__ out, int out_size)
{
    __shared__ unsigned char bp[TT*5];
    __shared__ float fch[256*5];
    const int lane = threadIdx.x;
    float trow[5] = {0,0,0,0,0};
    if (lane < 5) {
        #pragma unroll
        for (int p = 0; p < 5; p++) trow[p] = trans[lane*5 + p];
    }
    float fv[5];
    #pragma unroll
    for (int p = 0; p < 5; p++) fv[p] = (p == 3) ? 0.f : NEGV;

    for (int ch = 0; ch < TT/256; ch++) {
        const float* src = feats + ch*256*5;
        for (int i = lane; i < 256*5; i += 32) fch[i] = src[i];
        __syncwarp();
        for (int s = 0; s < 256; s++) {
            float best = fv[0] + trow[0]; int arg = 0;
            #pragma unroll
            for (int p = 1; p < 5; p++) { float v = fv[p] + trow[p]; if (v > best) { best = v; arg = p; } }
            float fe = (lane < 5) ? fch[s*5 + lane] : 0.f;
            float nv = best + fe;
            if (lane < 5) bp[(ch*256 + s)*5 + lane] = (unsigned char)arg;
            #pragma unroll
            for (int p = 0; p < 5; p++) fv[p] = __shfl_sync(0xFFFFFFFFu, nv, p);
        }
        __syncwarp();
    }
    float term = (lane < 5) ? (fv[lane] + trans[4*5 + lane]) : (4.f*NEGV);
    float t0 = __shfl_sync(0xFFFFFFFFu, term, 0);
    float t1 = __shfl_sync(0xFFFFFFFFu, term, 1);
    float t2 = __shfl_sync(0xFFFFFFFFu, term, 2);
    float t3 = __shfl_sync(0xFFFFFFFFu, term, 3);
    float t4 = __shfl_sync(0xFFFFFFFFu, term, 4);
    if (lane == 0) {
        float best = t0; int lbl = 0;
        if (t1 > best) { best = t1; lbl = 1; }
        if (t2 > best) { best = t2; lbl = 2; }
        if (t3 > best) { best = t3; lbl = 3; }
        if (t4 > best) { best = t4; lbl = 4; }
        if (out_size >= TT + 1) {
            int base = out_size - TT;
            out[0] = best;
            out[base + TT - 1] = (float)lbl;
            for (int t = TT - 2; t >= 0; t--) { lbl = bp[(t+1)*5 + lbl]; out[base + t] = (float)lbl; }
        } else if (out_size >= TT) {
            int base = out_size - TT;
            out[base + TT - 1] = (float)lbl;
            for (int t = TT - 2; t >= 0; t--) { lbl = bp[(t+1)*5 + lbl]; out[base + t] = (float)lbl; }
        } else if (out_size >= 1) {
            out[0] = best;
        }
    }
}

// ---------------- host launch ----------------
extern "C" void kernel_launch(void* const* d_in, const int* in_sizes, int n_in,
                              void* d_out, int out_size)
{
    const float* hours    = (const float*)d_in[0];
    const float* w_ih_l0  = (const float*)d_in[1];
    const float* w_hh_l0  = (const float*)d_in[2];
    const float* b_ih_l0  = (const float*)d_in[3];
    const float* b_hh_l0  = (const float*)d_in[4];
    const float* w_ih_l0r = (const float*)d_in[5];
    const float* w_hh_l0r = (const float*)d_in[6];
    const float* b_ih_l0r = (const float*)d_in[7];
    const float* b_hh_l0r = (const float*)d_in[8];
    const float* w_ih_l1  = (const float*)d_in[9];
    const float* w_hh_l1  = (const float*)d_in[10];
    const float* b_ih_l1  = (const float*)d_in[11];
    const float* b_hh_l1  = (const float*)d_in[12];
    const float* w_ih_l1r = (const float*)d_in[13];
    const float* w_hh_l1r = (const float*)d_in[14];
    const float* b_ih_l1r = (const float*)d_in[15];
    const float* b_hh_l1r = (const float*)d_in[16];
    const float* w_out    = (const float*)d_in[17];
    const float* b_out    = (const float*)d_in[18];
    const float* trans    = (const float*)d_in[19];

    float *xg0, *h0, *h1, *feats;
    cudaGetSymbolAddress((void**)&xg0,   g_xg);
    cudaGetSymbolAddress((void**)&h0,    g_h0);
    cudaGetSymbolAddress((void**)&h1,    g_h1);
    cudaGetSymbolAddress((void**)&feats, g_feats);
    float* xg1 = xg0 + (size_t)TT * G4H;

    cudaFuncSetAttribute(lstm_kernel, cudaFuncAttributeMaxDynamicSharedMemorySize, SMEM_LSTM);

    dim3 gemm_grid(G4H/BN, TT/BM);

    sgemm_bias<<<gemm_grid, 256>>>(hours, w_ih_l0,  b_ih_l0,  b_hh_l0,  xg0, TT, G4H, 512);
    sgemm_bias<<<gemm_grid, 256>>>(hours, w_ih_l0r, b_ih_l0r, b_hh_l0r, xg1, TT, G4H, 512);
    init_kernel<<<16, 256>>>();
    lstm_kernel<<<NBLK, 256, SMEM_LSTM>>>(xg0, xg1, w_hh_l0, w_hh_l0r, h0);

    sgemm_bias<<<gemm_grid, 256>>>(h0, w_ih_l1,  b_ih_l1,  b_hh_l1,  xg0, TT, G4H, 2048);
    sgemm_bias<<<gemm_grid, 256>>>(h0, w_ih_l1r, b_ih_l1r, b_hh_l1r, xg1, TT, G4H, 2048);
    init_kernel<<<16, 256>>>();
    lstm_kernel<<<NBLK, 256, SMEM_LSTM>>>(xg0, xg1, w_hh_l1, w_hh_l1r, h1);

    feats_kernel<<<TT, 256>>>(h1, w_out, b_out, feats);
    viterbi_kernel<<<1, 32>>>(feats, trans, (float*)d_out, out_size);
}

// round 16
// speedup vs baseline: 1.5344x; 1.5344x over previous
#include <cuda_runtime.h>
#include <cuda_bf16.h>
#include <math.h>

#define TT    8192
#define HD    1024
#define G4H   4096
#define NBLK  128               // 128 blocks * 4 warps/dir * 2 units/warp = 1024 units/dir
#define KREG  512               // k < 512 register-resident (4 float4 chunks/lane)
#define KSM   512               // k in [512,1024) in smem
// dynamic smem: weights[8 warps][8 rows][512] + hstage[2][1024]
#define OFF_HS    (8*8*KSM)             // float offset of h stage
#define SMEM_LSTM ((OFF_HS + 2*HD) * 4) // 139264 B

// ---------------- static device scratch ----------------
__device__ float    g_xg[2][TT][G4H];
__device__ float    g_h0[(size_t)TT*2048];
__device__ float    g_h1[(size_t)TT*2048];
__device__ float    g_feats[TT*5];
__device__ float    g_hbuf[2][2][HD];        // [dir][ping][H]
struct Ctr { unsigned v; unsigned pad[31]; };
__device__ Ctr      g_ctr2[2];               // one counter per direction, own 128B line

union F2 { float2 f; unsigned long long u; };

__device__ __forceinline__ unsigned ld_acq(const unsigned* p) {
    unsigned v;
    asm volatile("ld.acquire.gpu.global.u32 %0, [%1];" : "=r"(v) : "l"(p) : "memory");
    return v;
}
__device__ __forceinline__ void red_rel_add1(unsigned* p) {
    asm volatile("red.release.gpu.global.add.u32 [%0], 1;" :: "l"(p) : "memory");
}
__device__ __forceinline__ void bar_named(int id) {
    asm volatile("bar.sync %0, 128;" :: "r"(id) : "memory");
}
__device__ __forceinline__ void fma2(F2& acc, float ax, float ay, float bx, float by) {
    F2 a, b; a.f.x = ax; a.f.y = ay; b.f.x = bx; b.f.y = by;
    asm("fma.rn.f32x2 %0, %1, %2, %0;" : "+l"(acc.u) : "l"(a.u), "l"(b.u));
}

__global__ void init_kernel() {
    int i = blockIdx.x * blockDim.x + threadIdx.x;
    if (i < 2*2*HD) ((float*)g_hbuf)[i] = 0.f;
    if (i < 2) g_ctr2[i].v = 0u;
}

// ---------------- fp32 SGEMM, double-buffered, f32x2 FMA, float4 LDS ----------------
#define BM 128
#define BN 128
#define BK 16
__global__ void __launch_bounds__(256) sgemm_bias(
    const float* __restrict__ A, const float* __restrict__ W,
    const float* __restrict__ b1, const float* __restrict__ b2,
    float* __restrict__ C, int M, int N, int K)
{
    __shared__ float As[2][BK][BM+4];
    __shared__ float Bs[2][BK][BN+4];
    const int tid = threadIdx.x;
    const int bm0 = blockIdx.y * BM;
    const int bn0 = blockIdx.x * BN;
    const int tx = tid & 15, ty = tid >> 4;
    const int lrow = tid >> 2;
    const int lc4  = (tid & 3) * 4;

    F2 acc[8][4];
    #pragma unroll
    for (int i = 0; i < 8; i++)
        #pragma unroll
        for (int j = 0; j < 4; j++) acc[i][j].u = 0ull;

    float4 ra[2], rb[2];
    #pragma unroll
    for (int h = 0; h < 2; h++) {
        int row = lrow + h*64;
        ra[h] = *(const float4*)(A + (size_t)(bm0+row)*K + lc4);
        rb[h] = *(const float4*)(W + (size_t)(bn0+row)*K + lc4);
    }
    #pragma unroll
    for (int h = 0; h < 2; h++) {
        int row = lrow + h*64;
        As[0][lc4+0][row] = ra[h].x; As[0][lc4+1][row] = ra[h].y;
        As[0][lc4+2][row] = ra[h].z; As[0][lc4+3][row] = ra[h].w;
        Bs[0][lc4+0][row] = rb[h].x; Bs[0][lc4+1][row] = rb[h].y;
        Bs[0][lc4+2][row] = rb[h].z; Bs[0][lc4+3][row] = rb[h].w;
    }
    __syncthreads();

    int buf = 0;
    for (int k0 = BK; k0 <= K; k0 += BK) {
        if (k0 < K) {
            #pragma unroll
            for (int h = 0; h < 2; h++) {
                int row = lrow + h*64;
                ra[h] = *(const float4*)(A + (size_t)(bm0+row)*K + k0 + lc4);
                rb[h] = *(const float4*)(W + (size_t)(bn0+row)*K + k0 + lc4);
            }
        }
        #pragma unroll
        for (int kk = 0; kk < BK; kk++) {
            float4 a0 = ((const float4*)&As[buf][kk][ty*8])[0];
            float4 a1 = ((const float4*)&As[buf][kk][ty*8])[1];
            float4 b0 = ((const float4*)&Bs[buf][kk][tx*8])[0];
            float4 b1 = ((const float4*)&Bs[buf][kk][tx*8])[1];
            float a[8] = {a0.x, a0.y, a0.z, a0.w, a1.x, a1.y, a1.z, a1.w};
            F2 bp[4];
            bp[0].f.x = b0.x; bp[0].f.y = b0.y;
            bp[1].f.x = b0.z; bp[1].f.y = b0.w;
            bp[2].f.x = b1.x; bp[2].f.y = b1.y;
            bp[3].f.x = b1.z; bp[3].f.y = b1.w;
            #pragma unroll
            for (int i = 0; i < 8; i++) {
                F2 ap; ap.f.x = a[i]; ap.f.y = a[i];
                #pragma unroll
                for (int j = 0; j < 4; j++)
                    asm("fma.rn.f32x2 %0, %1, %2, %0;" : "+l"(acc[i][j].u) : "l"(ap.u), "l"(bp[j].u));
            }
        }
        if (k0 < K) {
            __syncthreads();
            int nb = buf ^ 1;
            #pragma unroll
            for (int h = 0; h < 2; h++) {
                int row = lrow + h*64;
                As[nb][lc4+0][row] = ra[h].x; As[nb][lc4+1][row] = ra[h].y;
                As[nb][lc4+2][row] = ra[h].z; As[nb][lc4+3][row] = ra[h].w;
                Bs[nb][lc4+0][row] = rb[h].x; Bs[nb][lc4+1][row] = rb[h].y;
                Bs[nb][lc4+2][row] = rb[h].z; Bs[nb][lc4+3][row] = rb[h].w;
            }
            __syncthreads();
            buf = nb;
        }
    }
    float bv[8];
    #pragma unroll
    for (int j = 0; j < 8; j++) { int n = bn0 + tx*8 + j; bv[j] = b1[n] + b2[n]; }
    #pragma unroll
    for (int i = 0; i < 8; i++) {
        size_t mrow = (size_t)(bm0 + ty*8 + i) * N;
        #pragma unroll
        for (int j = 0; j < 4; j++) {
            C[mrow + bn0 + tx*8 + 2*j + 0] = acc[i][j].f.x + bv[2*j+0];
            C[mrow + bn0 + tx*8 + 2*j + 1] = acc[i][j].f.y + bv[2*j+1];
        }
    }
}

// ---------------- persistent bidirectional LSTM (R8 signaling + tree reduce) ----------------
// 128 blocks x 8 warps; warps 0-3 fwd, 4-7 bwd; warp owns 2 units (8 whole gate
// rows). Per step: poll warp (gq==0) tight-spins (ld.acquire, converged), stages
// h L2->smem; ONE bar -> dots (reg+smem weights, f32x2) -> TREE reduce (lane l
// ends with row l&7's full sum, 9 shfl) -> lane-parallel acts -> lanes 0/1
// stcg h -> bar -> ONE red.release per block per dir -> hout store off path.
__global__ void __launch_bounds__(256, 1) lstm_kernel(
    const float* __restrict__ xgf, const float* __restrict__ xgb,
    const float* __restrict__ whf, const float* __restrict__ whb,
    float* __restrict__ hout)
{
    extern __shared__ float ws[];
    const int tid  = threadIdx.x;
    const int warp = tid >> 5;
    const int lane = tid & 31;
    const int dir  = warp >> 2;
    const int gq   = warp & 3;
    const int gtid = tid & 127;
    const int u0   = blockIdx.x * 8 + gq * 2;

    const float* wh = dir ? whb : whf;
    const float* xg = dir ? xgb : xgf;

    // ---- stage smem weight half (k in [512,1024)) ----
    for (int idx = tid; idx < 8*8*(KSM/4); idx += 256) {
        int w2 = idx >> 10;                 // warp slot 0..7
        int rr = (idx >> 7) & 7;            // row within warp
        int q  = idx & 127;                 // float4 within KSM
        int unit = blockIdx.x * 8 + (w2 & 3) * 2 + (rr & 1);
        int gate = rr >> 1;
        const float* src = ((w2 >> 2) ? whb : whf) + ((size_t)((gate << 10) + unit)) * HD;
        ((float4*)ws)[idx] = __ldg((const float4*)src + (KREG/4) + q);
    }
    // ---- register weight half (k < 512): wreg[8 rows][4 chunks] ----
    float4 wreg[8][4];
    #pragma unroll
    for (int r = 0; r < 8; r++) {
        int unit = u0 + (r & 1);
        int gate = r >> 1;
        const float4* src = (const float4*)(wh + ((size_t)((gate << 10) + unit)) * HD);
        #pragma unroll
        for (int i = 0; i < 4; i++) wreg[r][i] = __ldg(src + (i << 5) + lane);
    }
    __syncthreads();

    const float4* ws_warp = (const float4*)ws + warp * 8 * (KSM/4);
    float4* hs4 = (float4*)(ws + OFF_HS + dir * HD);
    const bool cl = (lane < 2);
    const int  myu = u0 + lane;             // lanes 0,1
    unsigned* ctr = &g_ctr2[dir].v;
    const int bid = 1 + dir;
    const int du = lane & 1;
    const int b0 = lane & 1, b1 = (lane >> 1) & 1, b2 = (lane >> 2) & 1;
    float creg = 0.f;

    #pragma unroll 1
    for (int t = 0; t < TT; t++) {
        const int tt = dir ? (TT-1-t) : t;
        // xg prefetch for lanes 0,1 (DRAM, issued before the wait)
        float xgv0=0.f, xgv1=0.f, xgv2=0.f, xgv3=0.f;
        if (cl) {
            const float* p = xg + (size_t)tt * G4H + myu;
            xgv0 = __ldg(p); xgv1 = __ldg(p+HD); xgv2 = __ldg(p+2*HD); xgv3 = __ldg(p+3*HD);
        }
        // poll warp: tight acquire spin, then stage h L2 -> smem
        if (gq == 0) {
            const unsigned tgt = (unsigned)t * (unsigned)NBLK;
            while (ld_acq(ctr) < tgt) { }
            const float4* hb4 = (const float4*)&g_hbuf[dir][t & 1][0];
            #pragma unroll
            for (int i = 0; i < 8; i++) hs4[(i << 5) + lane] = __ldcg(hb4 + (i << 5) + lane);
        }
        bar_named(bid);
        // h into registers from smem
        float4 hv[8];
        #pragma unroll
        for (int i = 0; i < 8; i++) hv[i] = hs4[(i << 5) + lane];
        // 8 complete gate-row dots: 4 chunks regs + 4 chunks smem, f32x2
        F2 acc[8];
        #pragma unroll
        for (int r = 0; r < 8; r++) acc[r].u = 0ull;
        #pragma unroll
        for (int r = 0; r < 8; r++) {
            #pragma unroll
            for (int i = 0; i < 4; i++) {
                float4 w = wreg[r][i];
                fma2(acc[r], w.x, w.y, hv[i].x, hv[i].y);
                fma2(acc[r], w.z, w.w, hv[i].z, hv[i].w);
            }
            const float4* w4s = ws_warp + r * (KSM/4);
            #pragma unroll
            for (int i = 0; i < 4; i++) {
                float4 v = w4s[(i << 5) + lane];
                fma2(acc[r], v.x, v.y, hv[4+i].x, hv[4+i].y);
                fma2(acc[r], v.z, v.w, hv[4+i].z, hv[4+i].w);
            }
        }
        // tree multi-value reduce: lane l ends with row (l&7)'s full sum (9 shfl)
        float s[8];
        #pragma unroll
        for (int r = 0; r < 8; r++) s[r] = acc[r].f.x + acc[r].f.y;
        float k4[4];
        #pragma unroll
        for (int i = 0; i < 4; i++) {
            float a  = b0 ? s[2*i+1] : s[2*i];
            float bs = b0 ? s[2*i]   : s[2*i+1];
            k4[i] = a + __shfl_xor_sync(0xFFFFFFFFu, bs, 1);
        }
        float k2[2];
        #pragma unroll
        for (int j = 0; j < 2; j++) {
            float a  = b1 ? k4[2*j+1] : k4[2*j];
            float bs = b1 ? k4[2*j]   : k4[2*j+1];
            k2[j] = a + __shfl_xor_sync(0xFFFFFFFFu, bs, 2);
        }
        float a3  = b2 ? k2[1] : k2[0];
        float bs3 = b2 ? k2[0] : k2[1];
        float k1 = a3 + __shfl_xor_sync(0xFFFFFFFFu, bs3, 4);
        k1 += __shfl_xor_sync(0xFFFFFFFFu, k1, 8);
        k1 += __shfl_xor_sync(0xFFFFFFFFu, k1, 16);
        // 8-lane parallel activations: lane l = row l (gate l>>1, unit du=l&1)
        float xg0s = __shfl_sync(0xFFFFFFFFu, xgv0, du);
        float xg1s = __shfl_sync(0xFFFFFFFFu, xgv1, du);
        float xg2s = __shfl_sync(0xFFFFFFFFu, xgv2, du);
        float xg3s = __shfl_sync(0xFFFFFFFFu, xgv3, du);
        int gsel = lane >> 1;
        float xgs = (gsel == 0) ? xg0s : (gsel == 1) ? xg1s : (gsel == 2) ? xg2s : xg3s;
        float raw = xgs + k1;
        float act = (gsel == 2) ? tanhf(raw) : 1.f / (1.f + expf(-raw));
        // gather per-unit gates and update (lanes 0,1)
        float ai = __shfl_sync(0xFFFFFFFFu, act, du);
        float af = __shfl_sync(0xFFFFFFFFu, act, 2 + du);
        float ag = __shfl_sync(0xFFFFFFFFu, act, 4 + du);
        float ao = __shfl_sync(0xFFFFFFFFu, act, 6 + du);
        float h = 0.f;
        if (cl) {
            creg = af * creg + ai * ag;
            h = ao * tanhf(creg);
            __stcg(&g_hbuf[dir][(t+1) & 1][myu], h);
        }
        bar_named(bid);
        if (gtid == 0) red_rel_add1(ctr);    // ONE arrival per block per dir
        // hout DRAM store off the signaling critical path
        if (cl) hout[(size_t)tt * 2048 + (dir << 10) + myu] = h;
    }
}

// ---------------- feats = h1 @ w_out^T + b_out (shuffle reduction) ----------------
__global__ void feats_kernel(const float* __restrict__ h1, const float* __restrict__ wout,
                             const float* __restrict__ bout, float* __restrict__ feats)
{
    __shared__ float red[5][8];
    int t = blockIdx.x, tid = threadIdx.x;
    int warp = tid >> 5, lane = tid & 31;
    const float* hrow = h1 + (size_t)t * 2048;
    float p[5] = {0,0,0,0,0};
    for (int k = tid; k < 2048; k += 256) {
        float hv = hrow[k];
        p[0] = fmaf(hv, __ldg(wout + 0*2048 + k), p[0]);
        p[1] = fmaf(hv, __ldg(wout + 1*2048 + k), p[1]);
        p[2] = fmaf(hv, __ldg(wout + 2*2048 + k), p[2]);
        p[3] = fmaf(hv, __ldg(wout + 3*2048 + k), p[3]);
        p[4] = fmaf(hv, __ldg(wout + 4*2048 + k), p[4]);
    }
    #pragma unroll
    for (int g = 0; g < 5; g++) {
        float s = p[g];
        #pragma unroll
        for (int off = 16; off; off >>= 1) s += __shfl_xor_sync(0xFFFFFFFFu, s, off);
        if (lane == 0) red[g][warp] = s;
    }
    __syncthreads();
    if (tid < 5) {
        float s = 0.f;
        #pragma unroll
        for (int i = 0; i < 8; i++) s += red[tid][i];
        feats[t*5 + tid] = s + bout[tid];
    }
}

// ---------------- Viterbi DP + backtrace ----------------
#define NEGV (-10000.0f)
__global__ void viterbi_kernel(const float* __restrict__ feats, const float* __restrict__ trans,
                               float* __restrict__ out, int out_size)
{
    __shared__ unsigned char bp[TT*5];
    __shared__ float fch[256*5];
    const int lane = threadIdx.x;
    float trow[5] = {0,0,0,0,0};
    if (lane < 5) {
        #pragma unroll
        for (int p = 0; p < 5; p++) trow[p] = trans[lane*5 + p];
    }
    float fv[5];
    #pragma unroll
    for (int p = 0; p < 5; p++) fv[p] = (p == 3) ? 0.f : NEGV;

    for (int ch = 0; ch < TT/256; ch++) {
        const float* src = feats + ch*256*5;
        for (int i = lane; i < 256*5; i += 32) fch[i] = src[i];
        __syncwarp();
        for (int s = 0; s < 256; s++) {
            float best = fv[0] + trow[0]; int arg = 0;
            #pragma unroll
            for (int p = 1; p < 5; p++) { float v = fv[p] + trow[p]; if (v > best) { best = v; arg = p; } }
            float fe = (lane < 5) ? fch[s*5 + lane] : 0.f;
            float nv = best + fe;
            if (lane < 5) bp[(ch*256 + s)*5 + lane] = (unsigned char)arg;
            #pragma unroll
            for (int p = 0; p < 5; p++) fv[p] = __shfl_sync(0xFFFFFFFFu, nv, p);
        }
        __syncwarp();
    }
    float term = (lane < 5) ? (fv[lane] + trans[4*5 + lane]) : (4.f*NEGV);
    float t0 = __shfl_sync(0xFFFFFFFFu, term, 0);
    float t1 = __shfl_sync(0xFFFFFFFFu, term, 1);
    float t2 = __shfl_sync(0xFFFFFFFFu, term, 2);
    float t3 = __shfl_sync(0xFFFFFFFFu, term, 3);
    float t4 = __shfl_sync(0xFFFFFFFFu, term, 4);
    if (lane == 0) {
        float best = t0; int lbl = 0;
        if (t1 > best) { best = t1; lbl = 1; }
        if (t2 > best) { best = t2; lbl = 2; }
        if (t3 > best) { best = t3; lbl = 3; }
        if (t4 > best) { best = t4; lbl = 4; }
        if (out_size >= TT + 1) {
            int base = out_size - TT;
            out[0] = best;
            out[base + TT - 1] = (float)lbl;
            for (int t = TT - 2; t >= 0; t--) { lbl = bp[(t+1)*5 + lbl]; out[base + t] = (float)lbl; }
        } else if (out_size >= TT) {
            int base = out_size - TT;
            out[base + TT - 1] = (float)lbl;
            for (int t = TT - 2; t >= 0; t--) { lbl = bp[(t+1)*5 + lbl]; out[base + t] = (float)lbl; }
        } else if (out_size >= 1) {
            out[0] = best;
        }
    }
}

// ---------------- host launch ----------------
extern "C" void kernel_launch(void* const* d_in, const int* in_sizes, int n_in,
                              void* d_out, int out_size)
{
    const float* hours    = (const float*)d_in[0];
    const float* w_ih_l0  = (const float*)d_in[1];
    const float* w_hh_l0  = (const float*)d_in[2];
    const float* b_ih_l0  = (const float*)d_in[3];
    const float* b_hh_l0  = (const float*)d_in[4];
    const float* w_ih_l0r = (const float*)d_in[5];
    const float* w_hh_l0r = (const float*)d_in[6];
    const float* b_ih_l0r = (const float*)d_in[7];
    const float* b_hh_l0r = (const float*)d_in[8];
    const float* w_ih_l1  = (const float*)d_in[9];
    const float* w_hh_l1  = (const float*)d_in[10];
    const float* b_ih_l1  = (const float*)d_in[11];
    const float* b_hh_l1  = (const float*)d_in[12];
    const float* w_ih_l1r = (const float*)d_in[13];
    const float* w_hh_l1r = (const float*)d_in[14];
    const float* b_ih_l1r = (const float*)d_in[15];
    const float* b_hh_l1r = (const float*)d_in[16];
    const float* w_out    = (const float*)d_in[17];
    const float* b_out    = (const float*)d_in[18];
    const float* trans    = (const float*)d_in[19];

    float *xg0, *h0, *h1, *feats;
    cudaGetSymbolAddress((void**)&xg0,   g_xg);
    cudaGetSymbolAddress((void**)&h0,    g_h0);
    cudaGetSymbolAddress((void**)&h1,    g_h1);
    cudaGetSymbolAddress((void**)&feats, g_feats);
    float* xg1 = xg0 + (size_t)TT * G4H;

    cudaFuncSetAttribute(lstm_kernel, cudaFuncAttributeMaxDynamicSharedMemorySize, SMEM_LSTM);

    dim3 gemm_grid(G4H/BN, TT/BM);

    sgemm_bias<<<gemm_grid, 256>>>(hours, w_ih_l0,  b_ih_l0,  b_hh_l0,  xg0, TT, G4H, 512);
    sgemm_bias<<<gemm_grid, 256>>>(hours, w_ih_l0r, b_ih_l0r, b_hh_l0r, xg1, TT, G4H, 512);
    init_kernel<<<16, 256>>>();
    lstm_kernel<<<NBLK, 256, SMEM_LSTM>>>(xg0, xg1, w_hh_l0, w_hh_l0r, h0);

    sgemm_bias<<<gemm_grid, 256>>>(h0, w_ih_l1,  b_ih_l1,  b_hh_l1,  xg0, TT, G4H, 2048);
    sgemm_bias<<<gemm_grid, 256>>>(h0, w_ih_l1r, b_ih_l1r, b_hh_l1r, xg1, TT, G4H, 2048);
    init_kernel<<<16, 256>>>();
    lstm_kernel<<<NBLK, 256, SMEM_LSTM>>>(xg0, xg1, w_hh_l1, w_hh_l1r, h1);

    feats_kernel<<<TT, 256>>>(h1, w_out, b_out, feats);
    viterbi_kernel<<<1, 32>>>(feats, trans, (float*)d_out, out_size);
}

// round 17
// speedup vs baseline: 1.6676x; 1.0868x over previous
#include <cuda_runtime.h>
#include <cuda_bf16.h>
#include <math.h>

#define TT    8192
#define HD    1024
#define G4H   4096
#define NBLK  128               // 64 blocks per direction (dir = blockIdx.x & 1)
#define NBD   64                // blocks per dir
#define KREG  512               // k < 512 register-resident (4 float4 chunks/lane)
#define KSM   512               // k in [512,1024) in smem
// dynamic smem: weights[8 warps][8 rows][512] + hstage[1024]
#define OFF_HS    (8*8*KSM)             // float offset of h stage
#define SMEM_LSTM ((OFF_HS + HD) * 4)   // 135168 B

// ---------------- static device scratch ----------------
__device__ float    g_xg[2][TT][G4H];
__device__ float    g_h0[(size_t)TT*2048];
__device__ float    g_h1[(size_t)TT*2048];
__device__ float    g_feats[TT*5];
__device__ float    g_hbuf[2][2][HD];        // [dir][ping][H]
struct Ctr { unsigned v; unsigned pad[31]; };
__device__ Ctr      g_ctr2[2];               // one counter per direction, own 128B line

union F2 { float2 f; unsigned long long u; };

__device__ __forceinline__ unsigned ld_acq(const unsigned* p) {
    unsigned v;
    asm volatile("ld.acquire.gpu.global.u32 %0, [%1];" : "=r"(v) : "l"(p) : "memory");
    return v;
}
__device__ __forceinline__ void red_rel_add1(unsigned* p) {
    asm volatile("red.release.gpu.global.add.u32 [%0], 1;" :: "l"(p) : "memory");
}
__device__ __forceinline__ void fma2(F2& acc, float ax, float ay, float bx, float by) {
    F2 a, b; a.f.x = ax; a.f.y = ay; b.f.x = bx; b.f.y = by;
    asm("fma.rn.f32x2 %0, %1, %2, %0;" : "+l"(acc.u) : "l"(a.u), "l"(b.u));
}

__global__ void init_kernel() {
    int i = blockIdx.x * blockDim.x + threadIdx.x;
    if (i < 2*2*HD) ((float*)g_hbuf)[i] = 0.f;
    if (i < 2) g_ctr2[i].v = 0u;
}

// ---------------- fp32 SGEMM, double-buffered, f32x2 FMA, float4 LDS ----------------
#define BM 128
#define BN 128
#define BK 16
__global__ void __launch_bounds__(256) sgemm_bias(
    const float* __restrict__ A, const float* __restrict__ W,
    const float* __restrict__ b1, const float* __restrict__ b2,
    float* __restrict__ C, int M, int N, int K)
{
    __shared__ float As[2][BK][BM+4];
    __shared__ float Bs[2][BK][BN+4];
    const int tid = threadIdx.x;
    const int bm0 = blockIdx.y * BM;
    const int bn0 = blockIdx.x * BN;
    const int tx = tid & 15, ty = tid >> 4;
    const int lrow = tid >> 2;
    const int lc4  = (tid & 3) * 4;

    F2 acc[8][4];
    #pragma unroll
    for (int i = 0; i < 8; i++)
        #pragma unroll
        for (int j = 0; j < 4; j++) acc[i][j].u = 0ull;

    float4 ra[2], rb[2];
    #pragma unroll
    for (int h = 0; h < 2; h++) {
        int row = lrow + h*64;
        ra[h] = *(const float4*)(A + (size_t)(bm0+row)*K + lc4);
        rb[h] = *(const float4*)(W + (size_t)(bn0+row)*K + lc4);
    }
    #pragma unroll
    for (int h = 0; h < 2; h++) {
        int row = lrow + h*64;
        As[0][lc4+0][row] = ra[h].x; As[0][lc4+1][row] = ra[h].y;
        As[0][lc4+2][row] = ra[h].z; As[0][lc4+3][row] = ra[h].w;
        Bs[0][lc4+0][row] = rb[h].x; Bs[0][lc4+1][row] = rb[h].y;
        Bs[0][lc4+2][row] = rb[h].z; Bs[0][lc4+3][row] = rb[h].w;
    }
    __syncthreads();

    int buf = 0;
    for (int k0 = BK; k0 <= K; k0 += BK) {
        if (k0 < K) {
            #pragma unroll
            for (int h = 0; h < 2; h++) {
                int row = lrow + h*64;
                ra[h] = *(const float4*)(A + (size_t)(bm0+row)*K + k0 + lc4);
                rb[h] = *(const float4*)(W + (size_t)(bn0+row)*K + k0 + lc4);
            }
        }
        #pragma unroll
        for (int kk = 0; kk < BK; kk++) {
            float4 a0 = ((const float4*)&As[buf][kk][ty*8])[0];
            float4 a1 = ((const float4*)&As[buf][kk][ty*8])[1];
            float4 b0 = ((const float4*)&Bs[buf][kk][tx*8])[0];
            float4 b1 = ((const float4*)&Bs[buf][kk][tx*8])[1];
            float a[8] = {a0.x, a0.y, a0.z, a0.w, a1.x, a1.y, a1.z, a1.w};
            F2 bp[4];
            bp[0].f.x = b0.x; bp[0].f.y = b0.y;
            bp[1].f.x = b0.z; bp[1].f.y = b0.w;
            bp[2].f.x = b1.x; bp[2].f.y = b1.y;
            bp[3].f.x = b1.z; bp[3].f.y = b1.w;
            #pragma unroll
            for (int i = 0; i < 8; i++) {
                F2 ap; ap.f.x = a[i]; ap.f.y = a[i];
                #pragma unroll
                for (int j = 0; j < 4; j++)
                    asm("fma.rn.f32x2 %0, %1, %2, %0;" : "+l"(acc[i][j].u) : "l"(ap.u), "l"(bp[j].u));
            }
        }
        if (k0 < K) {
            __syncthreads();
            int nb = buf ^ 1;
            #pragma unroll
            for (int h = 0; h < 2; h++) {
                int row = lrow + h*64;
                As[nb][lc4+0][row] = ra[h].x; As[nb][lc4+1][row] = ra[h].y;
                As[nb][lc4+2][row] = ra[h].z; As[nb][lc4+3][row] = ra[h].w;
                Bs[nb][lc4+0][row] = rb[h].x; Bs[nb][lc4+1][row] = rb[h].y;
                Bs[nb][lc4+2][row] = rb[h].z; Bs[nb][lc4+3][row] = rb[h].w;
            }
            __syncthreads();
            buf = nb;
        }
    }
    float bv[8];
    #pragma unroll
    for (int j = 0; j < 8; j++) { int n = bn0 + tx*8 + j; bv[j] = b1[n] + b2[n]; }
    #pragma unroll
    for (int i = 0; i < 8; i++) {
        size_t mrow = (size_t)(bm0 + ty*8 + i) * N;
        #pragma unroll
        for (int j = 0; j < 4; j++) {
            C[mrow + bn0 + tx*8 + 2*j + 0] = acc[i][j].f.x + bv[2*j+0];
            C[mrow + bn0 + tx*8 + 2*j + 1] = acc[i][j].f.y + bv[2*j+1];
        }
    }
}

// ---------------- persistent bidirectional LSTM (single-dir blocks) ----------------
// 128 blocks: dir = blockIdx.x & 1, bb = blockIdx.x >> 1 (64 blocks/dir).
// Warp w owns units u0 = bb*16 + w*2 + {0,1} of this dir (8 whole gate rows,
// r = gate*2 + du). Per step: warp 0 acquire-spins on the dir counter
// (target t*64), stages h L2->smem; __syncthreads -> dots (reg+smem, f32x2)
// -> tree reduce -> lane-parallel acts -> lanes 0/1 stcg h -> __syncthreads
// -> ONE red.release per block (64 arrivals/dir/step) -> hout store off path.
__global__ void __launch_bounds__(256, 1) lstm_kernel(
    const float* __restrict__ xgf, const float* __restrict__ xgb,
    const float* __restrict__ whf, const float* __restrict__ whb,
    float* __restrict__ hout)
{
    extern __shared__ float ws[];
    const int tid  = threadIdx.x;
    const int warp = tid >> 5;
    const int lane = tid & 31;
    const int dir  = blockIdx.x & 1;
    const int bb   = blockIdx.x >> 1;
    const int u0   = bb * 16 + warp * 2;

    const float* wh = dir ? whb : whf;
    const float* xg = dir ? xgb : xgf;

    // ---- stage smem weight half (k in [512,1024)): 64 rows of this dir ----
    for (int idx = tid; idx < 8*8*(KSM/4); idx += 256) {
        int w2 = idx >> 10;                 // warp slot 0..7
        int rr = (idx >> 7) & 7;            // row within warp
        int q  = idx & 127;                 // float4 within KSM
        int unit = bb * 16 + w2 * 2 + (rr & 1);
        int gate = rr >> 1;
        const float* src = wh + ((size_t)((gate << 10) + unit)) * HD;
        ((float4*)ws)[idx] = __ldg((const float4*)src + (KREG/4) + q);
    }
    // ---- register weight half (k < 512): wreg[8 rows][4 chunks] ----
    float4 wreg[8][4];
    #pragma unroll
    for (int r = 0; r < 8; r++) {
        int unit = u0 + (r & 1);
        int gate = r >> 1;
        const float4* src = (const float4*)(wh + ((size_t)((gate << 10) + unit)) * HD);
        #pragma unroll
        for (int i = 0; i < 4; i++) wreg[r][i] = __ldg(src + (i << 5) + lane);
    }
    __syncthreads();

    const float4* ws_warp = (const float4*)ws + warp * 8 * (KSM/4);
    float4* hs4 = (float4*)(ws + OFF_HS);
    const bool cl = (lane < 2);
    const int  myu = u0 + lane;             // lanes 0,1
    unsigned* ctr = &g_ctr2[dir].v;
    const int du = lane & 1;
    const int b0 = lane & 1, b1 = (lane >> 1) & 1, b2 = (lane >> 2) & 1;
    float creg = 0.f;

    #pragma unroll 1
    for (int t = 0; t < TT; t++) {
        const int tt = dir ? (TT-1-t) : t;
        // xg prefetch for lanes 0,1 (DRAM, issued before the wait)
        float xgv0=0.f, xgv1=0.f, xgv2=0.f, xgv3=0.f;
        if (cl) {
            const float* p = xg + (size_t)tt * G4H + myu;
            xgv0 = __ldg(p); xgv1 = __ldg(p+HD); xgv2 = __ldg(p+2*HD); xgv3 = __ldg(p+3*HD);
        }
        // warp 0: tight acquire spin on this dir's counter, then stage h L2 -> smem
        if (warp == 0) {
            const unsigned tgt = (unsigned)t * (unsigned)NBD;   // 64 arrivals/dir/step
            while (ld_acq(ctr) < tgt) { }
            const float4* hb4 = (const float4*)&g_hbuf[dir][t & 1][0];
            #pragma unroll
            for (int i = 0; i < 8; i++) hs4[(i << 5) + lane] = __ldcg(hb4 + (i << 5) + lane);
        }
        __syncthreads();
        // h into registers from smem
        float4 hv[8];
        #pragma unroll
        for (int i = 0; i < 8; i++) hv[i] = hs4[(i << 5) + lane];
        // 8 complete gate-row dots: 4 chunks regs + 4 chunks smem, f32x2
        F2 acc[8];
        #pragma unroll
        for (int r = 0; r < 8; r++) acc[r].u = 0ull;
        #pragma unroll
        for (int r = 0; r < 8; r++) {
            #pragma unroll
            for (int i = 0; i < 4; i++) {
                float4 w = wreg[r][i];
                fma2(acc[r], w.x, w.y, hv[i].x, hv[i].y);
                fma2(acc[r], w.z, w.w, hv[i].z, hv[i].w);
            }
            const float4* w4s = ws_warp + r * (KSM/4);
            #pragma unroll
            for (int i = 0; i < 4; i++) {
                float4 v = w4s[(i << 5) + lane];
                fma2(acc[r], v.x, v.y, hv[4+i].x, hv[4+i].y);
                fma2(acc[r], v.z, v.w, hv[4+i].z, hv[4+i].w);
            }
        }
        // tree multi-value reduce: lane l ends with row (l&7)'s full sum (9 shfl)
        float s[8];
        #pragma unroll
        for (int r = 0; r < 8; r++) s[r] = acc[r].f.x + acc[r].f.y;
        float k4[4];
        #pragma unroll
        for (int i = 0; i < 4; i++) {
            float a  = b0 ? s[2*i+1] : s[2*i];
            float bs = b0 ? s[2*i]   : s[2*i+1];
            k4[i] = a + __shfl_xor_sync(0xFFFFFFFFu, bs, 1);
        }
        float k2[2];
        #pragma unroll
        for (int j = 0; j < 2; j++) {
            float a  = b1 ? k4[2*j+1] : k4[2*j];
            float bs = b1 ? k4[2*j]   : k4[2*j+1];
            k2[j] = a + __shfl_xor_sync(0xFFFFFFFFu, bs, 2);
        }
        float a3  = b2 ? k2[1] : k2[0];
        float bs3 = b2 ? k2[0] : k2[1];
        float k1 = a3 + __shfl_xor_sync(0xFFFFFFFFu, bs3, 4);
        k1 += __shfl_xor_sync(0xFFFFFFFFu, k1, 8);
        k1 += __shfl_xor_sync(0xFFFFFFFFu, k1, 16);
        // 8-lane parallel activations: lane l = row l (gate l>>1, unit du=l&1)
        float xg0s = __shfl_sync(0xFFFFFFFFu, xgv0, du);
        float xg1s = __shfl_sync(0xFFFFFFFFu, xgv1, du);
        float xg2s = __shfl_sync(0xFFFFFFFFu, xgv2, du);
        float xg3s = __shfl_sync(0xFFFFFFFFu, xgv3, du);
        int gsel = lane >> 1;
        float xgs = (gsel == 0) ? xg0s : (gsel == 1) ? xg1s : (gsel == 2) ? xg2s : xg3s;
        float raw = xgs + k1;
        float act = (gsel == 2) ? tanhf(raw) : 1.f / (1.f + expf(-raw));
        // gather per-unit gates and update (lanes 0,1)
        float ai = __shfl_sync(0xFFFFFFFFu, act, du);
        float af = __shfl_sync(0xFFFFFFFFu, act, 2 + du);
        float ag = __shfl_sync(0xFFFFFFFFu, act, 4 + du);
        float ao = __shfl_sync(0xFFFFFFFFu, act, 6 + du);
        float h = 0.f;
        if (cl) {
            creg = af * creg + ai * ag;
            h = ao * tanhf(creg);
            __stcg(&g_hbuf[dir][(t+1) & 1][myu], h);
        }
        __syncthreads();                     // CTA hb: h stores before the arrival
        if (tid == 0) red_rel_add1(ctr);     // ONE arrival per block (64/dir/step)
        // hout DRAM store off the signaling critical path
        if (cl) hout[(size_t)tt * 2048 + (dir << 10) + myu] = h;
    }
}

// ---------------- feats = h1 @ w_out^T + b_out (shuffle reduction) ----------------
__global__ void feats_kernel(const float* __restrict__ h1, const float* __restrict__ wout,
                             const float* __restrict__ bout, float* __restrict__ feats)
{
    __shared__ float red[5][8];
    int t = blockIdx.x, tid = threadIdx.x;
    int warp = tid >> 5, lane = tid & 31;
    const float* hrow = h1 + (size_t)t * 2048;
    float p[5] = {0,0,0,0,0};
    for (int k = tid; k < 2048; k += 256) {
        float hv = hrow[k];
        p[0] = fmaf(hv, __ldg(wout + 0*2048 + k), p[0]);
        p[1] = fmaf(hv, __ldg(wout + 1*2048 + k), p[1]);
        p[2] = fmaf(hv, __ldg(wout + 2*2048 + k), p[2]);
        p[3] = fmaf(hv, __ldg(wout + 3*2048 + k), p[3]);
        p[4] = fmaf(hv, __ldg(wout + 4*2048 + k), p[4]);
    }
    #pragma unroll
    for (int g = 0; g < 5; g++) {
        float s = p[g];
        #pragma unroll
        for (int off = 16; off; off >>= 1) s += __shfl_xor_sync(0xFFFFFFFFu, s, off);
        if (lane == 0) red[g][warp] = s;
    }
    __syncthreads();
    if (tid < 5) {
        float s = 0.f;
        #pragma unroll
        for (int i = 0; i < 8; i++) s += red[tid][i];
        feats[t*5 + tid] = s + bout[tid];
    }
}

// ---------------- Viterbi DP + backtrace ----------------
#define NEGV (-10000.0f)
__global__ void viterbi_kernel(const float* __restrict__ feats, const float* __restrict__ trans,
                               float* __restrict__ out, int out_size)
{
    __shared__ unsigned char bp[TT*5];
    __shared__ float fch[256*5];
    const int lane = threadIdx.x;
    float trow[5] = {0,0,0,0,0};
    if (lane < 5) {
        #pragma unroll
        for (int p = 0; p < 5; p++) trow[p] = trans[lane*5 + p];
    }
    float fv[5];
    #pragma unroll
    for (int p = 0; p < 5; p++) fv[p] = (p == 3) ? 0.f : NEGV;

    for (int ch = 0; ch < TT/256; ch++) {
        const float* src = feats + ch*256*5;
        for (int i = lane; i < 256*5; i += 32) fch[i] = src[i];
        __syncwarp();
        for (int s = 0; s < 256; s++) {
            float best = fv[0] + trow[0]; int arg = 0;
            #pragma unroll
            for (int p = 1; p < 5; p++) { float v = fv[p] + trow[p]; if (v > best) { best = v; arg = p; } }
            float fe = (lane < 5) ? fch[s*5 + lane] : 0.f;
            float nv = best + fe;
            if (lane < 5) bp[(ch*256 + s)*5 + lane] = (unsigned char)arg;
            #pragma unroll
            for (int p = 0; p < 5; p++) fv[p] = __shfl_sync(0xFFFFFFFFu, nv, p);
        }
        __syncwarp();
    }
    float term = (lane < 5) ? (fv[lane] + trans[4*5 + lane]) : (4.f*NEGV);
    float t0 = __shfl_sync(0xFFFFFFFFu, term, 0);
    float t1 = __shfl_sync(0xFFFFFFFFu, term, 1);
    float t2 = __shfl_sync(0xFFFFFFFFu, term, 2);
    float t3 = __shfl_sync(0xFFFFFFFFu, term, 3);
    float t4 = __shfl_sync(0xFFFFFFFFu, term, 4);
    if (lane == 0) {
        float best = t0; int lbl = 0;
        if (t1 > best) { best = t1; lbl = 1; }
        if (t2 > best) { best = t2; lbl = 2; }
        if (t3 > best) { best = t3; lbl = 3; }
        if (t4 > best) { best = t4; lbl = 4; }
        if (out_size >= TT + 1) {
            int base = out_size - TT;
            out[0] = best;
            out[base + TT - 1] = (float)lbl;
            for (int t = TT - 2; t >= 0; t--) { lbl = bp[(t+1)*5 + lbl]; out[base + t] = (float)lbl; }
        } else if (out_size >= TT) {
            int base = out_size - TT;
            out[base + TT - 1] = (float)lbl;
            for (int t = TT - 2; t >= 0; t--) { lbl = bp[(t+1)*5 + lbl]; out[base + t] = (float)lbl; }
        } else if (out_size >= 1) {
            out[0] = best;
        }
    }
}

// ---------------- host launch ----------------
extern "C" void kernel_launch(void* const* d_in, const int* in_sizes, int n_in,
                              void* d_out, int out_size)
{
    const float* hours    = (const float*)d_in[0];
    const float* w_ih_l0  = (const float*)d_in[1];
    const float* w_hh_l0  = (const float*)d_in[2];
    const float* b_ih_l0  = (const float*)d_in[3];
    const float* b_hh_l0  = (const float*)d_in[4];
    const float* w_ih_l0r = (const float*)d_in[5];
    const float* w_hh_l0r = (const float*)d_in[6];
    const float* b_ih_l0r = (const float*)d_in[7];
    const float* b_hh_l0r = (const float*)d_in[8];
    const float* w_ih_l1  = (const float*)d_in[9];
    const float* w_hh_l1  = (const float*)d_in[10];
    const float* b_ih_l1  = (const float*)d_in[11];
    const float* b_hh_l1  = (const float*)d_in[12];
    const float* w_ih_l1r = (const float*)d_in[13];
    const float* w_hh_l1r = (const float*)d_in[14];
    const float* b_ih_l1r = (const float*)d_in[15];
    const float* b_hh_l1r = (const float*)d_in[16];
    const float* w_out    = (const float*)d_in[17];
    const float* b_out    = (const float*)d_in[18];
    const float* trans    = (const float*)d_in[19];

    float *xg0, *h0, *h1, *feats;
    cudaGetSymbolAddress((void**)&xg0,   g_xg);
    cudaGetSymbolAddress((void**)&h0,    g_h0);
    cudaGetSymbolAddress((void**)&h1,    g_h1);
    cudaGetSymbolAddress((void**)&feats, g_feats);
    float* xg1 = xg0 + (size_t)TT * G4H;

    cudaFuncSetAttribute(lstm_kernel, cudaFuncAttributeMaxDynamicSharedMemorySize, SMEM_LSTM);

    dim3 gemm_grid(G4H/BN, TT/BM);

    sgemm_bias<<<gemm_grid, 256>>>(hours, w_ih_l0,  b_ih_l0,  b_hh_l0,  xg0, TT, G4H, 512);
    sgemm_bias<<<gemm_grid, 256>>>(hours, w_ih_l0r, b_ih_l0r, b_hh_l0r, xg1, TT, G4H, 512);
    init_kernel<<<16, 256>>>();
    lstm_kernel<<<NBLK, 256, SMEM_LSTM>>>(xg0, xg1, w_hh_l0, w_hh_l0r, h0);

    sgemm_bias<<<gemm_grid, 256>>>(h0, w_ih_l1,  b_ih_l1,  b_hh_l1,  xg0, TT, G4H, 2048);
    sgemm_bias<<<gemm_grid, 256>>>(h0, w_ih_l1r, b_ih_l1r, b_hh_l1r, xg1, TT, G4H, 2048);
    init_kernel<<<16, 256>>>();
    lstm_kernel<<<NBLK, 256, SMEM_LSTM>>>(xg0, xg1, w_hh_l1, w_hh_l1r, h1);

    feats_kernel<<<TT, 256>>>(h1, w_out, b_out, feats);
    viterbi_kernel<<<1, 32>>>(feats, trans, (float*)d_out, out_size);
}